// round 15
// baseline (speedup 1.0000x reference)
#include <cuda_runtime.h>
#include <cuda_bf16.h>

// Problem constants: H=32, T=8192, D=128
#define RP_H 32
#define RP_T 8192
#define RP_D 128
#define RP_ROWS (RP_H * RP_T)          // 262144
#define RP_HPW 4                       // heads per warp (cos/sin register reuse)
#define RP_HG (RP_H / RP_HPW)          // 8 head groups
#define RP_THREADS 256                 // 8 warps/block
#define RP_TPB 8                       // t-values per chunk (1 per warp)
#define RP_TBLOCKS (RP_T / RP_TPB)     // 1024
#define RP_CHUNKS (RP_HG * RP_TBLOCKS) // 8192 logical work chunks
#define RP_SMS 152                     // GB300 SM count
#define RP_BPSM 6                      // blocks/SM (matches launch_bounds min-blocks)
#define RP_BLOCKS (RP_SMS * RP_BPSM)   // 912: exactly one wave, persistent

// R6/R14 inner body (best verified 43.5us) wrapped in a persistent grid-stride
// loop: grid = one full wave (912 CTAs), each CTA processes ~9 chunks
// back-to-back. Removes inter-wave transitions and the ragged 10th-wave drain;
// per-SM MLP stays saturated until the single final drain.
__global__ __launch_bounds__(RP_THREADS, RP_BPSM) void rope_minmax_kernel(
    const float* __restrict__ x,
    const float* __restrict__ cosb,
    const float* __restrict__ sinb,
    float* __restrict__ out,
    float* __restrict__ obs_max,
    float* __restrict__ obs_min)
{
    const unsigned FULL = 0xffffffffu;
    const int wid  = threadIdx.x >> 5;
    const int lane = threadIdx.x & 31;
    const float sign = (lane < 16) ? -1.0f : 1.0f;

    for (int chunk = blockIdx.x; chunk < RP_CHUNKS; chunk += RP_BLOCKS) {
        int hg = chunk >> 10;                  // head group 0..7
        int tb = chunk & (RP_TBLOCKS - 1);     // t-block within group
        int t  = tb * RP_TPB + wid;            // this warp's t
        int h0 = hg * RP_HPW;                  // first head

        // ---- DRAM-bound x loads first: 4 independent LDG.128.CS ----
        float4 v[RP_HPW];
        #pragma unroll
        for (int j = 0; j < RP_HPW; j++) {
            size_t row = (size_t)(h0 + j) * RP_T + t;
            v[j] = __ldcs(reinterpret_cast<const float4*>(x + row * RP_D) + lane);
        }

        // ---- table loads once per chunk (default policy: L2-resident) ----
        float4 c = reinterpret_cast<const float4*>(cosb + (size_t)t * RP_D)[lane];
        float4 s = reinterpret_cast<const float4*>(sinb + (size_t)t * RP_D)[lane];

        float4 sgs = make_float4(sign * s.x, sign * s.y, sign * s.z, sign * s.w);
        float mx[RP_HPW], mn[RP_HPW];

        #pragma unroll
        for (int j = 0; j < RP_HPW; j++) {
            // partner half (elements i +/- 64) lives in lane ^ 16
            float4 p;
            p.x = __shfl_xor_sync(FULL, v[j].x, 16);
            p.y = __shfl_xor_sync(FULL, v[j].y, 16);
            p.z = __shfl_xor_sync(FULL, v[j].z, 16);
            p.w = __shfl_xor_sync(FULL, v[j].w, 16);

            float4 o;
            o.x = fmaf(p.x, sgs.x, v[j].x * c.x);
            o.y = fmaf(p.y, sgs.y, v[j].y * c.y);
            o.z = fmaf(p.z, sgs.z, v[j].z * c.z);
            o.w = fmaf(p.w, sgs.w, v[j].w * c.w);

            size_t row = (size_t)(h0 + j) * RP_T + t;
            __stcs(reinterpret_cast<float4*>(out + row * RP_D) + lane, o);

            mx[j] = fmaxf(fmaxf(o.x, o.y), fmaxf(o.z, o.w));
            mn[j] = fminf(fminf(o.x, o.y), fminf(o.z, o.w));
        }

        // ---- 4 interleaved butterfly reductions ----
        #pragma unroll
        for (int off = 16; off > 0; off >>= 1) {
            #pragma unroll
            for (int j = 0; j < RP_HPW; j++) {
                mx[j] = fmaxf(mx[j], __shfl_xor_sync(FULL, mx[j], off));
                mn[j] = fminf(mn[j], __shfl_xor_sync(FULL, mn[j], off));
            }
        }

        // lanes 0..3 store their row's stats
        if (lane < RP_HPW) {
            size_t row = (size_t)(h0 + lane) * RP_T + t;
            obs_max[row] = mx[lane];
            obs_min[row] = mn[lane];
        }
    }
}

extern "C" void kernel_launch(void* const* d_in, const int* in_sizes, int n_in,
                              void* d_out, int out_size) {
    // Input order: x, scale_x (unused), cos, scale_cos (unused), sin, scale_sin (unused)
    const float* x    = (const float*)d_in[0];
    const float* cosb = (const float*)d_in[2];
    const float* sinb = (const float*)d_in[4];

    float* out     = (float*)d_out;                    // H*T*D
    float* obs_max = out + (size_t)RP_ROWS * RP_D;     // H*T
    float* obs_min = obs_max + (size_t)RP_ROWS;        // H*T

    rope_minmax_kernel<<<RP_BLOCKS, RP_THREADS>>>(x, cosb, sinb, out, obs_max, obs_min);
}

// round 16
// speedup vs baseline: 1.1526x; 1.1526x over previous
#include <cuda_runtime.h>
#include <cuda_bf16.h>

// Problem constants: H=32, T=8192, D=128
#define RP_H 32
#define RP_T 8192
#define RP_D 128
#define RP_ROWS (RP_H * RP_T)          // 262144
#define RP_HPW 4                       // heads per warp (cos/sin register reuse)
#define RP_HG (RP_H / RP_HPW)          // 8 head groups
#define RP_THREADS 256                 // 8 warps/block
#define RP_TPB 8                       // t-values per block (1 per warp)
#define RP_TBLOCKS (RP_T / RP_TPB)     // 1024
#define RP_BLOCKS (RP_HG * RP_TBLOCKS) // 8192

// FINAL (verified twice: 43.49us / 43.52us — ~93% of achievable mixed-R/W HBM
// roofline for the mandatory 268MB of traffic):
// - one warp = one t, 4 heads; cos/sin loaded ONCE per warp, reused for the
//   4 x-rows (4x less L2 table traffic — LTS service was the binding resource)
// - x: 4 front-batched LDG.128.CS (read-once, evict-first, MLP=4/warp)
// - out: STG.128.CS (write-once streaming)
// - rotation partner (i +/- 64) via shfl_xor(16): x read exactly once
// - warps in a block take consecutive t -> dense 4KB chunks per head
// - __launch_bounds__(256,6): regs=40, 48 warps/SM resident
// Rejected by measurement: t-major remap (R3), st.wt (R8), L2 evict_last pin
// (R10), 256-bit v8 ops (R12), redux.sync tail (R13, tie), persistent grid (R15).
__global__ __launch_bounds__(RP_THREADS, 6) void rope_minmax_kernel(
    const float* __restrict__ x,
    const float* __restrict__ cosb,
    const float* __restrict__ sinb,
    float* __restrict__ out,
    float* __restrict__ obs_max,
    float* __restrict__ obs_min)
{
    const unsigned FULL = 0xffffffffu;
    int wid  = threadIdx.x >> 5;
    int lane = threadIdx.x & 31;
    int hg   = blockIdx.x >> 10;                 // head group 0..7
    int tb   = blockIdx.x & (RP_TBLOCKS - 1);    // t-block within group
    int t    = tb * RP_TPB + wid;                // this warp's t
    int h0   = hg * RP_HPW;                      // first head

    // ---- DRAM-bound x loads first: 4 independent LDG.128.CS (4 heads, same t) ----
    float4 v[RP_HPW];
    #pragma unroll
    for (int j = 0; j < RP_HPW; j++) {
        size_t row = (size_t)(h0 + j) * RP_T + t;
        v[j] = __ldcs(reinterpret_cast<const float4*>(x + row * RP_D) + lane);
    }

    // ---- table loads once (default policy: reused across heads, L2-resident) ----
    float4 c = reinterpret_cast<const float4*>(cosb + (size_t)t * RP_D)[lane];
    float4 s = reinterpret_cast<const float4*>(sinb + (size_t)t * RP_D)[lane];

    float sign = (lane < 16) ? -1.0f : 1.0f;
    float4 sgs = make_float4(sign * s.x, sign * s.y, sign * s.z, sign * s.w);
    float mx[RP_HPW], mn[RP_HPW];

    #pragma unroll
    for (int j = 0; j < RP_HPW; j++) {
        // partner half (elements i +/- 64) lives in lane ^ 16
        float4 p;
        p.x = __shfl_xor_sync(FULL, v[j].x, 16);
        p.y = __shfl_xor_sync(FULL, v[j].y, 16);
        p.z = __shfl_xor_sync(FULL, v[j].z, 16);
        p.w = __shfl_xor_sync(FULL, v[j].w, 16);

        float4 o;
        o.x = fmaf(p.x, sgs.x, v[j].x * c.x);
        o.y = fmaf(p.y, sgs.y, v[j].y * c.y);
        o.z = fmaf(p.z, sgs.z, v[j].z * c.z);
        o.w = fmaf(p.w, sgs.w, v[j].w * c.w);

        size_t row = (size_t)(h0 + j) * RP_T + t;
        __stcs(reinterpret_cast<float4*>(out + row * RP_D) + lane, o);

        mx[j] = fmaxf(fmaxf(o.x, o.y), fmaxf(o.z, o.w));
        mn[j] = fminf(fminf(o.x, o.y), fminf(o.z, o.w));
    }

    // ---- 4 interleaved butterfly reductions (ILP hides SHFL latency) ----
    #pragma unroll
    for (int off = 16; off > 0; off >>= 1) {
        #pragma unroll
        for (int j = 0; j < RP_HPW; j++) {
            mx[j] = fmaxf(mx[j], __shfl_xor_sync(FULL, mx[j], off));
            mn[j] = fminf(mn[j], __shfl_xor_sync(FULL, mn[j], off));
        }
    }

    // After butterfly every lane holds the result: lanes 0..3 store their row's stats.
    if (lane < RP_HPW) {
        size_t row = (size_t)(h0 + lane) * RP_T + t;
        obs_max[row] = mx[lane];
        obs_min[row] = mn[lane];
    }
}

extern "C" void kernel_launch(void* const* d_in, const int* in_sizes, int n_in,
                              void* d_out, int out_size) {
    // Input order: x, scale_x (unused), cos, scale_cos (unused), sin, scale_sin (unused)
    const float* x    = (const float*)d_in[0];
    const float* cosb = (const float*)d_in[2];
    const float* sinb = (const float*)d_in[4];

    float* out     = (float*)d_out;                    // H*T*D
    float* obs_max = out + (size_t)RP_ROWS * RP_D;     // H*T
    float* obs_min = obs_max + (size_t)RP_ROWS;        // H*T

    rope_minmax_kernel<<<RP_BLOCKS, RP_THREADS>>>(x, cosb, sinb, out, obs_max, obs_min);
}

// round 17
// speedup vs baseline: 1.1941x; 1.0360x over previous
#include <cuda_runtime.h>
#include <cuda_bf16.h>

// Problem constants: H=32, T=8192, D=128
#define RP_H 32
#define RP_T 8192
#define RP_D 128
#define RP_ROWS (RP_H * RP_T)          // 262144
#define RP_HPW 4                       // heads per warp (cos/sin register reuse)
#define RP_HG (RP_H / RP_HPW)          // 8 head groups
#define RP_THREADS 256                 // 8 warps/block
#define RP_TPB 8                       // t-values per block (1 per warp)
#define RP_TBLOCKS (RP_T / RP_TPB)     // 1024
#define RP_BLOCKS (RP_HG * RP_TBLOCKS) // 8192

// FINAL — converged at the sustained mixed-R/W HBM roofline.
// Same-binary bench spread: 43.49 / 43.52 / 45.09 us (run noise ~±1.6us);
// ncu stable at 38.9-39.7us, DRAM 72-73%, all compute pipes <26%.
//
// Structure:
// - one warp = one t, 4 heads; cos/sin loaded ONCE per warp, reused for the
//   4 x-rows (4x less L2 table traffic — LTS service was the binding resource)
// - x: 4 front-batched LDG.128.CS (read-once, evict-first, MLP=4/warp),
//   issued BEFORE the L2-hit table loads (L1tex queue ordering)
// - out: STG.128.CS (write-once streaming)
// - rotation partner (i +/- 64) via shfl_xor(16): x read exactly once
// - warps in a block take consecutive t -> dense 4KB chunks per head
// - __launch_bounds__(256,6): regs=40, 48 warps/SM resident
//
// Rejected by measurement: t-major remap (R3), st.wt (R8), L2 evict_last pin
// (R10), 256-bit v8 ops (R12), redux.sync tail (R13, tie), persistent grid
// (R15), HPW=8 (R7, tie at lower occupancy).
__global__ __launch_bounds__(RP_THREADS, 6) void rope_minmax_kernel(
    const float* __restrict__ x,
    const float* __restrict__ cosb,
    const float* __restrict__ sinb,
    float* __restrict__ out,
    float* __restrict__ obs_max,
    float* __restrict__ obs_min)
{
    const unsigned FULL = 0xffffffffu;
    int wid  = threadIdx.x >> 5;
    int lane = threadIdx.x & 31;
    int hg   = blockIdx.x >> 10;                 // head group 0..7
    int tb   = blockIdx.x & (RP_TBLOCKS - 1);    // t-block within group
    int t    = tb * RP_TPB + wid;                // this warp's t
    int h0   = hg * RP_HPW;                      // first head

    // ---- DRAM-bound x loads first: 4 independent LDG.128.CS (4 heads, same t) ----
    float4 v[RP_HPW];
    #pragma unroll
    for (int j = 0; j < RP_HPW; j++) {
        size_t row = (size_t)(h0 + j) * RP_T + t;
        v[j] = __ldcs(reinterpret_cast<const float4*>(x + row * RP_D) + lane);
    }

    // ---- table loads once (default policy: reused across heads, L2-resident) ----
    float4 c = reinterpret_cast<const float4*>(cosb + (size_t)t * RP_D)[lane];
    float4 s = reinterpret_cast<const float4*>(sinb + (size_t)t * RP_D)[lane];

    float sign = (lane < 16) ? -1.0f : 1.0f;
    float4 sgs = make_float4(sign * s.x, sign * s.y, sign * s.z, sign * s.w);
    float mx[RP_HPW], mn[RP_HPW];

    #pragma unroll
    for (int j = 0; j < RP_HPW; j++) {
        // partner half (elements i +/- 64) lives in lane ^ 16
        float4 p;
        p.x = __shfl_xor_sync(FULL, v[j].x, 16);
        p.y = __shfl_xor_sync(FULL, v[j].y, 16);
        p.z = __shfl_xor_sync(FULL, v[j].z, 16);
        p.w = __shfl_xor_sync(FULL, v[j].w, 16);

        float4 o;
        o.x = fmaf(p.x, sgs.x, v[j].x * c.x);
        o.y = fmaf(p.y, sgs.y, v[j].y * c.y);
        o.z = fmaf(p.z, sgs.z, v[j].z * c.z);
        o.w = fmaf(p.w, sgs.w, v[j].w * c.w);

        size_t row = (size_t)(h0 + j) * RP_T + t;
        __stcs(reinterpret_cast<float4*>(out + row * RP_D) + lane, o);

        mx[j] = fmaxf(fmaxf(o.x, o.y), fmaxf(o.z, o.w));
        mn[j] = fminf(fminf(o.x, o.y), fminf(o.z, o.w));
    }

    // ---- 4 interleaved butterfly reductions (ILP hides SHFL latency) ----
    #pragma unroll
    for (int off = 16; off > 0; off >>= 1) {
        #pragma unroll
        for (int j = 0; j < RP_HPW; j++) {
            mx[j] = fmaxf(mx[j], __shfl_xor_sync(FULL, mx[j], off));
            mn[j] = fminf(mn[j], __shfl_xor_sync(FULL, mn[j], off));
        }
    }

    // After butterfly every lane holds the result: lanes 0..3 store their row's stats.
    if (lane < RP_HPW) {
        size_t row = (size_t)(h0 + lane) * RP_T + t;
        obs_max[row] = mx[lane];
        obs_min[row] = mn[lane];
    }
}

extern "C" void kernel_launch(void* const* d_in, const int* in_sizes, int n_in,
                              void* d_out, int out_size) {
    // Input order: x, scale_x (unused), cos, scale_cos (unused), sin, scale_sin (unused)
    const float* x    = (const float*)d_in[0];
    const float* cosb = (const float*)d_in[2];
    const float* sinb = (const float*)d_in[4];

    float* out     = (float*)d_out;                    // H*T*D
    float* obs_max = out + (size_t)RP_ROWS * RP_D;     // H*T
    float* obs_min = obs_max + (size_t)RP_ROWS;        // H*T

    rope_minmax_kernel<<<RP_BLOCKS, RP_THREADS>>>(x, cosb, sinb, out, obs_max, obs_min);
}